// round 7
// baseline (speedup 1.0000x reference)
#include <cuda_runtime.h>
#include <cstdint>
#include <cstddef>

#define BB 4
#define HH 128
#define WW 128
#define NP 9
#define PTOT (BB*HH*WW)

// ---------------------------------------------------------------------------
// Scratch
// ---------------------------------------------------------------------------
__device__ float  g_t1 [(size_t)PTOT * 64];     // tf32-rounded
__device__ float  g_t2 [(size_t)PTOT * 128];    // tf32-rounded
// fragment-ordered tf32 weights (attn: gemm-style; convs: thread-major packed)
__device__ uint32_t g_wKf[9 * 4096];
__device__ uint32_t g_wVf[9 * 4096];
__device__ uint32_t g_wQf[4096];
__device__ uint32_t g_wF1f[4096];
__device__ uint32_t g_wc2f[18 * 5120];          // [t*2+cb][ks][lane*20 + nf*2 + reg]
__device__ uint32_t g_wc3f[18 * 5120];          // [t*2+ch][ks][lane*20 + nf*2 + reg]

// ---------------------------------------------------------------------------
// helpers
// ---------------------------------------------------------------------------
__device__ __forceinline__ uint32_t tf32b(float x) {
    uint32_t u;
    asm("cvt.rna.tf32.f32 %0, %1;" : "=r"(u) : "f"(x));
    return u;
}
__device__ __forceinline__ float tf32r(float x) { return __uint_as_float(tf32b(x)); }

__device__ __forceinline__ void mma8(float* c, const uint32_t* a, const uint32_t* b) {
    asm volatile(
        "mma.sync.aligned.m16n8k8.row.col.f32.tf32.tf32.f32 "
        "{%0,%1,%2,%3}, {%4,%5,%6,%7}, {%8,%9}, {%0,%1,%2,%3};"
        : "+f"(c[0]), "+f"(c[1]), "+f"(c[2]), "+f"(c[3])
        : "r"(a[0]), "r"(a[1]), "r"(a[2]), "r"(a[3]),
          "r"(b[0]), "r"(b[1]));
}

__device__ __forceinline__ void cp16(void* dst_smem, const void* src) {
    uint32_t d = (uint32_t)__cvta_generic_to_shared(dst_smem);
    asm volatile("cp.async.cg.shared.global [%0], [%1], 16;" :: "r"(d), "l"(src) : "memory");
}
__device__ __forceinline__ void cp_commit() { asm volatile("cp.async.commit_group;" ::: "memory"); }
__device__ __forceinline__ void cp_wait0()  { asm volatile("cp.async.wait_group 0;"  ::: "memory"); }

// gemm-style 64-wide warp step (used by attn_fused; unchanged layout)
__device__ __forceinline__ void gemm64(float (&acc)[8][4], const uint32_t* Bl,
                                       const float* A0, const float* A8)
{
    #pragma unroll
    for (int ks = 0; ks < 8; ks++) {
        uint32_t a[4];
        a[0] = __float_as_uint(A0[ks * 8]);
        a[1] = __float_as_uint(A8[ks * 8]);
        a[2] = __float_as_uint(A0[ks * 8 + 4]);
        a[3] = __float_as_uint(A8[ks * 8 + 4]);
        #pragma unroll
        for (int nf = 0; nf < 8; nf++) {
            uint2 bv = *(const uint2*)&Bl[(ks * 8 + nf) * 64];
            uint32_t br[2] = {bv.x, bv.y};
            mma8(acc[nf], a, br);
        }
    }
}

// channel bit-permutation for conv halo: pos = {c[5:4], c[1:0], c[3], c[2]}
__device__ __forceinline__ int cperm(int c) {
    return ((c >> 4) << 4) | ((c & 3) << 2) | (((c >> 3) & 1) << 1) | ((c >> 2) & 1);
}

// ---------------------------------------------------------------------------
// Prep: shuffle all weights into fragment order (tf32-rounded)
// ---------------------------------------------------------------------------
__global__ __launch_bounds__(256) void prep_w(
    const float* __restrict__ K_P, const float* __restrict__ V_P,
    const float* __restrict__ Q_P, const float* __restrict__ F1,
    const float* __restrict__ W2, const float* __restrict__ W3)
{
    int i = blockIdx.x * 256 + threadIdx.x;
    if (i < 73728) {                               // K_P / V_P [64,576] (gemm-style)
        const float* src = (i < 36864) ? K_P : V_P;
        uint32_t* dst = (i < 36864) ? g_wKf : g_wVf;
        int j = (i < 36864) ? i : i - 36864;
        int k = j / 576, n = j % 576;
        int nt = n >> 6, nl = n & 63;
        int pos = ((k >> 3) * 8 + (nl >> 3)) * 64 + (((nl & 7) << 2) | (k & 3)) * 2 + ((k & 7) >> 2);
        dst[nt * 4096 + pos] = tf32b(src[j]);
    } else if (i < 81920) {                        // Q_P / ff1 [64,64] (gemm-style)
        int j = i - 73728;
        const float* src = (j < 4096) ? Q_P : F1;
        uint32_t* dst = (j < 4096) ? g_wQf : g_wF1f;
        int jj = j & 4095;
        int k = jj >> 6, n = jj & 63;
        int pos = ((k >> 3) * 8 + (n >> 3)) * 64 + (((n & 7) << 2) | (k & 3)) * 2 + ((k & 7) >> 2);
        dst[pos] = tf32b(src[jj]);
    } else if (i < 155648) {                       // ff2 [9][64][128] (packed, COUT-split)
        int j = i - 81920;
        int t = j >> 13, k = (j >> 7) & 63, n = j & 127;
        int cb = n >> 6, nl = n & 63;
        int ks = k >> 3, nf = nl >> 3;
        int ln = ((nl & 7) << 2) | (k & 3);
        int reg = (k & 7) >> 2;
        g_wc2f[(size_t)(t * 2 + cb) * 5120 + ks * 640 + ln * 20 + nf * 2 + reg] = tf32b(W2[j]);
    } else {                                       // ff3 [9][128][64] (packed, CIN-chunked)
        int j = i - 155648;
        int t = j >> 13, k = (j >> 6) & 127, n = j & 63;
        int ch = k >> 6, kl = k & 63;
        int ks = kl >> 3, nf = n >> 3;
        int ln = ((n & 7) << 2) | (kl & 3);
        int reg = (kl & 7) >> 2;
        g_wc3f[(size_t)(t * 2 + ch) * 5120 + ks * 640 + ln * 20 + nf * 2 + reg] = tf32b(W3[j]);
    }
}

// ---------------------------------------------------------------------------
// Fully fused: K/V/Q projections + tap attention + softmax + ff1 (as R6).
// ---------------------------------------------------------------------------
__global__ __launch_bounds__(256) void attn_fused(
    const float* __restrict__ x,
    const uint32_t* __restrict__ wQ, const uint32_t* __restrict__ wK,
    const uint32_t* __restrict__ wV, const uint32_t* __restrict__ wF1,
    const float* __restrict__ bias1, float* __restrict__ t1)
{
    constexpr int HW2 = 18, PST = 68;
    extern __shared__ char smraw[];
    float*    halo = (float*)smraw;                        // 180*68 floats
    uint32_t* Bf   = (uint32_t*)(smraw + 180 * PST * 4);   // 2 x 4096 uints

    const int x0 = blockIdx.x * 16;
    const int y0 = blockIdx.y * 8;
    const int b  = blockIdx.z;
    const int tid = threadIdx.x;
    const int warp = tid >> 5, lane = tid & 31;
    const int lr = lane >> 2, lc = lane & 3;

    #pragma unroll
    for (int i = 0; i < 4; i++) { int o = (tid + i * 256) * 4; cp16(Bf + o, wQ + o); }
    cp_commit();

    for (int idx = tid * 4; idx < 180 * 64; idx += 1024) {
        int c = idx & 63;
        int sp = idx >> 6;
        int hy = sp / HW2, hx = sp - hy * HW2;
        int gy = y0 + hy - 1, gx = x0 + hx - 1;
        float4 v = make_float4(0.f, 0.f, 0.f, 0.f);
        if ((unsigned)gy < HH && (unsigned)gx < WW)
            v = *(const float4*)(x + (((size_t)b * HH + gy) * WW + gx) * 64 + c);
        float* d = halo + sp * PST + c;
        d[0] = tf32r(v.x); d[1] = tf32r(v.y); d[2] = tf32r(v.z); d[3] = tf32r(v.w);
    }
    cp_wait0();
    __syncthreads();

    const int off0 = (warp * HW2 + lr) * PST;
    const int off8 = (warp * HW2 + lr + 8) * PST;

    float q[8][4];
    float sc[NP][4];

    {   // Q GEMM (center)
        #pragma unroll
        for (int i = 0; i < 4; i++) { int o = (tid + i * 256) * 4; cp16(Bf + 4096 + o, wK + o); }
        cp_commit();

        const int toff = (1 * HW2 + 1) * PST;
        float acc[8][4] = {};
        gemm64(acc, Bf + lane * 2, halo + off0 + toff + lc, halo + off8 + toff + lc);
        #pragma unroll
        for (int nf = 0; nf < 8; nf++)
            #pragma unroll
            for (int j = 0; j < 4; j++) q[nf][j] = acc[nf][j];
        cp_wait0();
        __syncthreads();
    }

    #pragma unroll
    for (int t = 0; t < NP; t++) {
        {
            const uint32_t* nsrc = (t < 8) ? wK + (t + 1) * 4096 : wV;
            uint32_t* nb = Bf + (t & 1) * 4096;
            #pragma unroll
            for (int i = 0; i < 4; i++) { int o = (tid + i * 256) * 4; cp16(nb + o, nsrc + o); }
            cp_commit();
        }
        const uint32_t* Bl = Bf + ((t + 1) & 1) * 4096 + lane * 2;
        const int toff = ((t / 3) * HW2 + (t % 3)) * PST;
        float acc[8][4] = {};
        gemm64(acc, Bl, halo + off0 + toff + lc, halo + off8 + toff + lc);

        float p[4] = {0.f, 0.f, 0.f, 0.f};
        #pragma unroll
        for (int nf = 0; nf < 8; nf++) {
            const int hd = nf >> 2;
            p[hd]     += acc[nf][0] * q[nf][0] + acc[nf][1] * q[nf][1];
            p[2 + hd] += acc[nf][2] * q[nf][2] + acc[nf][3] * q[nf][3];
        }
        #pragma unroll
        for (int v = 0; v < 4; v++) {
            p[v] += __shfl_xor_sync(0xffffffffu, p[v], 1);
            p[v] += __shfl_xor_sync(0xffffffffu, p[v], 2);
            sc[t][v] = p[v] * (1.0f / 3.0f);
        }
        cp_wait0();
        __syncthreads();
    }

    #pragma unroll
    for (int v = 0; v < 4; v++) {
        float m = sc[0][v];
        #pragma unroll
        for (int t = 1; t < NP; t++) m = fmaxf(m, sc[t][v]);
        float sum = 0.f;
        #pragma unroll
        for (int t = 0; t < NP; t++) { float e = __expf(sc[t][v] - m); sc[t][v] = e; sum += e; }
        const float inv = 1.0f / sum;
        #pragma unroll
        for (int t = 0; t < NP; t++) sc[t][v] *= inv;
    }

    float attn[8][4] = {};
    #pragma unroll
    for (int t = 0; t < NP; t++) {
        {
            const uint32_t* nsrc = (t < 8) ? wV + (t + 1) * 4096 : wF1;
            uint32_t* nb = Bf + ((t + 1) & 1) * 4096;
            #pragma unroll
            for (int i = 0; i < 4; i++) { int o = (tid + i * 256) * 4; cp16(nb + o, nsrc + o); }
            cp_commit();
        }
        const uint32_t* Bl = Bf + (t & 1) * 4096 + lane * 2;
        const int toff = ((t / 3) * HW2 + (t % 3)) * PST;
        float acc[8][4] = {};
        gemm64(acc, Bl, halo + off0 + toff + lc, halo + off8 + toff + lc);

        #pragma unroll
        for (int nf = 0; nf < 8; nf++) {
            const int hd = nf >> 2;
            attn[nf][0] += sc[t][hd]     * acc[nf][0];
            attn[nf][1] += sc[t][hd]     * acc[nf][1];
            attn[nf][2] += sc[t][2 + hd] * acc[nf][2];
            attn[nf][3] += sc[t][2 + hd] * acc[nf][3];
        }
        cp_wait0();
        __syncthreads();
    }

    float* Ast = halo;
    #pragma unroll
    for (int nf = 0; nf < 8; nf++) {
        int col = nf * 8 + lc * 2;
        *(float2*)&Ast[(warp * 16 + lr) * PST + col] =
            make_float2(tf32r(attn[nf][0]), tf32r(attn[nf][1]));
        *(float2*)&Ast[(warp * 16 + lr + 8) * PST + col] =
            make_float2(tf32r(attn[nf][2]), tf32r(attn[nf][3]));
    }
    __syncthreads();

    float acc[8][4] = {};
    gemm64(acc, Bf + 4096 + lane * 2,
           Ast + (warp * 16 + lr) * PST + lc,
           Ast + (warp * 16 + lr + 8) * PST + lc);

    const int ygl = y0 + warp;
    const size_t p0 = ((size_t)b * HH + ygl) * WW + x0 + lr;
    const size_t p1 = p0 + 8;
    #pragma unroll
    for (int nf = 0; nf < 8; nf++) {
        int col = nf * 8 + lc * 2;
        float b0 = bias1[col], b1 = bias1[col + 1];
        *(float2*)(t1 + p0 * 64 + col) = make_float2(
            tf32r(fmaxf(acc[nf][0] + b0, 0.f)), tf32r(fmaxf(acc[nf][1] + b1, 0.f)));
        *(float2*)(t1 + p1 * 64 + col) = make_float2(
            tf32r(fmaxf(acc[nf][2] + b0, 0.f)), tf32r(fmaxf(acc[nf][3] + b1, 0.f)));
    }
}

// ---------------------------------------------------------------------------
// 3x3 conv, vectorized implicit GEMM. 8x16 tile, 128 threads, COUT_BLK=64.
// Channel-permuted halo (A via LDS.128, row stride 80) + thread-major packed
// weights (B via LDS.128, lane stride 20). COUT split across gridz (SPLIT).
// grid = (W/16, H/8, B*SPLIT)
// ---------------------------------------------------------------------------
template <int CIN, int COUT_TOT, int SPLIT, bool ROUND>
__global__ __launch_bounds__(128, 2) void conv_tf32(
    const float* __restrict__ in, const uint32_t* __restrict__ wfrag,
    const float* __restrict__ bias, float* __restrict__ out)
{
    constexpr int HW2 = 18, PST = 80;
    constexpr int HALO_F = 10 * HW2 * PST;      // 14400 floats
    constexpr int CHUNKS = CIN / 64;
    constexpr int WTAP = 5120;                  // uints per (tap, chunk|cb)
    constexpr int CPT = WTAP / 4 / 128;         // 10 cp16 per thread
    constexpr int MFS = 2;

    extern __shared__ char smraw[];
    float*    halo = (float*)smraw;
    uint32_t* Bf   = (uint32_t*)(smraw + HALO_F * 4);   // 2 x WTAP

    const int x0 = blockIdx.x * 16;
    const int y0 = blockIdx.y * 8;
    const int b  = blockIdx.z / SPLIT;
    const int cb = blockIdx.z % SPLIT;
    const int co0 = cb * 64;
    const int tid = threadIdx.x;
    const int warp = tid >> 5, lane = tid & 31;
    const int lr = lane >> 2, lc = lane & 3;

    float acc[MFS][8][4] = {};

    int pixoff[MFS][2];
    #pragma unroll
    for (int mf = 0; mf < MFS; mf++)
        #pragma unroll
        for (int r8 = 0; r8 < 2; r8++) {
            int m = warp * 32 + mf * 16 + r8 * 8 + lr;
            int py = m >> 4, px = m & 15;
            pixoff[mf][r8] = (py * HW2 + px) * PST + lc * 4;
        }

    for (int ch = 0; ch < CHUNKS; ch++) {
        const int cin0 = ch * 64;
        __syncthreads();   // prior chunk fully consumed

        // prime tap 0 (overlaps halo staging)
        {
            const uint32_t* src = wfrag + (size_t)(0 * CHUNKS * SPLIT + ch + cb) * WTAP;
            #pragma unroll
            for (int i = 0; i < CPT; i++) { int o = (tid + i * 128) * 4; cp16(Bf + o, src + o); }
            cp_commit();
        }

        // halo with channel permutation (scatter 4 scalar STS per float4)
        for (int idx = tid * 4; idx < 10 * HW2 * 64; idx += 128 * 4) {
            int c = idx & 63;
            int sp = idx >> 6;
            int hy = sp / HW2, hx = sp - hy * HW2;
            int gy = y0 + hy - 1, gx = x0 + hx - 1;
            float4 v = make_float4(0.f, 0.f, 0.f, 0.f);
            if ((unsigned)gy < HH && (unsigned)gx < WW)
                v = *(const float4*)(in + (((size_t)b * HH + gy) * WW + gx) * CIN + cin0 + c);
            float* row = halo + sp * PST;
            row[cperm(c)]     = v.x;
            row[cperm(c + 1)] = v.y;
            row[cperm(c + 2)] = v.z;
            row[cperm(c + 3)] = v.w;
        }
        cp_wait0();
        __syncthreads();

        for (int t = 0; t < 9; t++) {
            if (t < 8) {
                uint32_t* nb = Bf + ((t + 1) & 1) * WTAP;
                const uint32_t* src = wfrag + (size_t)((t + 1) * CHUNKS * SPLIT + ch + cb) * WTAP;
                #pragma unroll
                for (int i = 0; i < CPT; i++) { int o = (tid + i * 128) * 4; cp16(nb + o, src + o); }
                cp_commit();
            }

            const uint32_t* Bc = Bf + (t & 1) * WTAP;
            const int toff = ((t / 3) * HW2 + (t % 3)) * PST;

            #pragma unroll
            for (int gp = 0; gp < 4; gp++) {
                // A: one LDS.128 per (mf, row-half) covers ks = 2gp, 2gp+1
                float4 fA[MFS][2];
                #pragma unroll
                for (int mf = 0; mf < MFS; mf++) {
                    fA[mf][0] = *(const float4*)(halo + pixoff[mf][0] + toff + gp * 16);
                    fA[mf][1] = *(const float4*)(halo + pixoff[mf][1] + toff + gp * 16);
                }
                #pragma unroll
                for (int kh = 0; kh < 2; kh++) {
                    const int ks = gp * 2 + kh;
                    uint32_t a[MFS][4];
                    #pragma unroll
                    for (int mf = 0; mf < MFS; mf++) {
                        if (kh == 0) {
                            a[mf][0] = __float_as_uint(fA[mf][0].x);
                            a[mf][1] = __float_as_uint(fA[mf][1].x);
                            a[mf][2] = __float_as_uint(fA[mf][0].y);
                            a[mf][3] = __float_as_uint(fA[mf][1].y);
                        } else {
                            a[mf][0] = __float_as_uint(fA[mf][0].z);
                            a[mf][1] = __float_as_uint(fA[mf][1].z);
                            a[mf][2] = __float_as_uint(fA[mf][0].w);
                            a[mf][3] = __float_as_uint(fA[mf][1].w);
                        }
                    }
                    const uint32_t* bbase = Bc + ks * 640 + lane * 20;
                    #pragma unroll
                    for (int j = 0; j < 4; j++) {
                        uint4 bv = *(const uint4*)(bbase + j * 4);
                        uint32_t br0[2] = {bv.x, bv.y};
                        uint32_t br1[2] = {bv.z, bv.w};
                        #pragma unroll
                        for (int mf = 0; mf < MFS; mf++) {
                            mma8(acc[mf][2 * j],     a[mf], br0);
                            mma8(acc[mf][2 * j + 1], a[mf], br1);
                        }
                    }
                }
            }

            if (t < 8) { cp_wait0(); __syncthreads(); }
        }
    }

    #pragma unroll
    for (int mf = 0; mf < MFS; mf++) {
        #pragma unroll
        for (int r8 = 0; r8 < 2; r8++) {
            int m = warp * 32 + mf * 16 + r8 * 8 + lr;
            int py = m >> 4, px = m & 15;
            int y = y0 + py, xx = x0 + px;
            size_t base = (((size_t)b * HH + y) * WW + xx) * COUT_TOT + co0;
            #pragma unroll
            for (int nf = 0; nf < 8; nf++) {
                int n = nf * 8 + lc * 2;
                float vx = fmaxf(acc[mf][nf][r8 * 2 + 0] + bias[co0 + n], 0.f);
                float vy = fmaxf(acc[mf][nf][r8 * 2 + 1] + bias[co0 + n + 1], 0.f);
                if (ROUND) { vx = tf32r(vx); vy = tf32r(vy); }
                *(float2*)(out + base + n) = make_float2(vx, vy);
            }
        }
    }
}

// ---------------------------------------------------------------------------
// Launch
// ---------------------------------------------------------------------------
extern "C" void kernel_launch(void* const* d_in, const int* in_sizes, int n_in,
                              void* d_out, int out_size)
{
    const float* x      = (const float*)d_in[0];
    const float* K_P    = (const float*)d_in[1];
    const float* V_P    = (const float*)d_in[2];
    const float* Q_P    = (const float*)d_in[3];
    const float* ff1_k  = (const float*)d_in[4];
    const float* ff1_b  = (const float*)d_in[5];
    const float* ff2_k  = (const float*)d_in[6];
    const float* ff2_b  = (const float*)d_in[7];
    const float* ff3_k  = (const float*)d_in[8];
    const float* ff3_b  = (const float*)d_in[9];
    float* out = (float*)d_out;

    float *t1, *t2;
    uint32_t *wKf, *wVf, *wQf, *wF1f, *wc2f, *wc3f;
    cudaGetSymbolAddress((void**)&t1,   g_t1);
    cudaGetSymbolAddress((void**)&t2,   g_t2);
    cudaGetSymbolAddress((void**)&wKf,  g_wKf);
    cudaGetSymbolAddress((void**)&wVf,  g_wVf);
    cudaGetSymbolAddress((void**)&wQf,  g_wQf);
    cudaGetSymbolAddress((void**)&wF1f, g_wF1f);
    cudaGetSymbolAddress((void**)&wc2f, g_wc2f);
    cudaGetSymbolAddress((void**)&wc3f, g_wc3f);

    const int FUSED_SMEM = 180 * 68 * 4 + 2 * 4096 * 4;    // 81728
    const int CONV_SMEM  = 180 * 80 * 4 + 2 * 5120 * 4;    // 98560

    cudaFuncSetAttribute(attn_fused, cudaFuncAttributeMaxDynamicSharedMemorySize, FUSED_SMEM);
    cudaFuncSetAttribute((conv_tf32<64, 128, 2, true>),  cudaFuncAttributeMaxDynamicSharedMemorySize, CONV_SMEM);
    cudaFuncSetAttribute((conv_tf32<128, 64, 1, false>), cudaFuncAttributeMaxDynamicSharedMemorySize, CONV_SMEM);

    prep_w<<<896, 256>>>(K_P, V_P, Q_P, ff1_k, ff2_k, ff3_k);

    // Fused projections + attention + ff1
    attn_fused<<<dim3(WW / 16, HH / 8, BB), 256, FUSED_SMEM>>>(
        x, wQf, wKf, wVf, wF1f, ff1_b, t1);

    // Convs (conv2: COUT split across blocks; conv3: CIN chunked)
    conv_tf32<64, 128, 2, true><<<dim3(WW / 16, HH / 8, BB * 2), 128, CONV_SMEM>>>(t1, wc2f, ff2_b, t2);
    conv_tf32<128, 64, 1, false><<<dim3(WW / 16, HH / 8, BB), 128, CONV_SMEM>>>(t2, wc3f, ff3_b, out);
}

// round 8
// speedup vs baseline: 1.1459x; 1.1459x over previous
#include <cuda_runtime.h>
#include <cstdint>
#include <cstddef>

#define BB 4
#define HH 128
#define WW 128
#define NP 9
#define PTOT (BB*HH*WW)

// ---------------------------------------------------------------------------
// Scratch
// ---------------------------------------------------------------------------
__device__ float  g_t1 [(size_t)PTOT * 64];     // tf32-rounded
__device__ float  g_t2 [(size_t)PTOT * 128];    // tf32-rounded
// fragment-ordered tf32 weights (all gemm-style 64-col tiles of 4096 uints)
__device__ uint32_t g_wKf[9 * 4096];
__device__ uint32_t g_wVf[9 * 4096];
__device__ uint32_t g_wQf[4096];
__device__ uint32_t g_wF1f[4096];
__device__ uint32_t g_wc2f[18 * 4096];          // [t*2+cb][sec][64]  (COUT split)
__device__ uint32_t g_wc3f[18 * 4096];          // [t*2+ch][sec][64]  (CIN chunked)

// ---------------------------------------------------------------------------
// helpers
// ---------------------------------------------------------------------------
__device__ __forceinline__ uint32_t tf32b(float x) {
    uint32_t u;
    asm("cvt.rna.tf32.f32 %0, %1;" : "=r"(u) : "f"(x));
    return u;
}
__device__ __forceinline__ float tf32r(float x) { return __uint_as_float(tf32b(x)); }

__device__ __forceinline__ void mma8(float* c, const uint32_t* a, const uint32_t* b) {
    asm volatile(
        "mma.sync.aligned.m16n8k8.row.col.f32.tf32.tf32.f32 "
        "{%0,%1,%2,%3}, {%4,%5,%6,%7}, {%8,%9}, {%0,%1,%2,%3};"
        : "+f"(c[0]), "+f"(c[1]), "+f"(c[2]), "+f"(c[3])
        : "r"(a[0]), "r"(a[1]), "r"(a[2]), "r"(a[3]),
          "r"(b[0]), "r"(b[1]));
}

__device__ __forceinline__ void cp16(void* dst_smem, const void* src) {
    uint32_t d = (uint32_t)__cvta_generic_to_shared(dst_smem);
    asm volatile("cp.async.cg.shared.global [%0], [%1], 16;" :: "r"(d), "l"(src) : "memory");
}
__device__ __forceinline__ void cp_commit() { asm volatile("cp.async.commit_group;" ::: "memory"); }
__device__ __forceinline__ void cp_wait0()  { asm volatile("cp.async.wait_group 0;"  ::: "memory"); }
__device__ __forceinline__ void cp_wait1()  { asm volatile("cp.async.wait_group 1;"  ::: "memory"); }

// gemm-style 64-wide warp step: m-frag 16 rows, 8 n-frags.
__device__ __forceinline__ void gemm64(float (&acc)[8][4], const uint32_t* Bl,
                                       const float* A0, const float* A8)
{
    #pragma unroll
    for (int ks = 0; ks < 8; ks++) {
        uint32_t a[4];
        a[0] = __float_as_uint(A0[ks * 8]);
        a[1] = __float_as_uint(A8[ks * 8]);
        a[2] = __float_as_uint(A0[ks * 8 + 4]);
        a[3] = __float_as_uint(A8[ks * 8 + 4]);
        #pragma unroll
        for (int nf = 0; nf < 8; nf++) {
            uint2 bv = *(const uint2*)&Bl[(ks * 8 + nf) * 64];
            uint32_t br[2] = {bv.x, bv.y};
            mma8(acc[nf], a, br);
        }
    }
}

// ---------------------------------------------------------------------------
// Prep: shuffle all weights into fragment order (tf32-rounded)
// ---------------------------------------------------------------------------
__global__ __launch_bounds__(256) void prep_w(
    const float* __restrict__ K_P, const float* __restrict__ V_P,
    const float* __restrict__ Q_P, const float* __restrict__ F1,
    const float* __restrict__ W2, const float* __restrict__ W3)
{
    int i = blockIdx.x * 256 + threadIdx.x;
    if (i < 73728) {                               // K_P / V_P [64,576]
        const float* src = (i < 36864) ? K_P : V_P;
        uint32_t* dst = (i < 36864) ? g_wKf : g_wVf;
        int j = (i < 36864) ? i : i - 36864;
        int k = j / 576, n = j % 576;
        int nt = n >> 6, nl = n & 63;
        int pos = ((k >> 3) * 8 + (nl >> 3)) * 64 + (((nl & 7) << 2) | (k & 3)) * 2 + ((k & 7) >> 2);
        dst[nt * 4096 + pos] = tf32b(src[j]);
    } else if (i < 81920) {                        // Q_P / ff1 [64,64]
        int j = i - 73728;
        const float* src = (j < 4096) ? Q_P : F1;
        uint32_t* dst = (j < 4096) ? g_wQf : g_wF1f;
        int jj = j & 4095;
        int k = jj >> 6, n = jj & 63;
        int pos = ((k >> 3) * 8 + (n >> 3)) * 64 + (((n & 7) << 2) | (k & 3)) * 2 + ((k & 7) >> 2);
        dst[pos] = tf32b(src[jj]);
    } else if (i < 155648) {                       // ff2 [9][64][128] -> COUT-split tiles
        int j = i - 81920;
        int t = j >> 13, k = (j >> 7) & 63, n = j & 127;
        int cb = n >> 6, nl = n & 63;
        int pos = ((k >> 3) * 8 + (nl >> 3)) * 64 + (((nl & 7) << 2) | (k & 3)) * 2 + ((k & 7) >> 2);
        g_wc2f[(size_t)(t * 2 + cb) * 4096 + pos] = tf32b(W2[j]);
    } else {                                       // ff3 [9][128][64] -> CIN-chunk tiles
        int j = i - 155648;
        int t = j >> 13, k = (j >> 6) & 127, n = j & 63;
        int ch = k >> 6, kl = k & 63;
        int pos = ((kl >> 3) * 8 + (n >> 3)) * 64 + (((n & 7) << 2) | (kl & 3)) * 2 + ((kl & 7) >> 2);
        g_wc3f[(size_t)(t * 2 + ch) * 4096 + pos] = tf32b(W3[j]);
    }
}

// ---------------------------------------------------------------------------
// Fully fused attention with ONLINE softmax: Q GEMM, then per tap t one stage
// computing K_t GEMM -> scores -> running-max rescale -> V_t GEMM -> weighted
// accumulate. 11 barrier stages instead of 20. Weight slots: 4 x 16KB; Q in
// slot0 (reclaimed), K/V pairs ping-pong {1,2} / {3,0}, ff1 -> slot3.
// ---------------------------------------------------------------------------
__global__ __launch_bounds__(256) void attn_fused(
    const float* __restrict__ x,
    const uint32_t* __restrict__ wQ, const uint32_t* __restrict__ wK,
    const uint32_t* __restrict__ wV, const uint32_t* __restrict__ wF1,
    const float* __restrict__ bias1, float* __restrict__ t1)
{
    constexpr int HW2 = 18, PST = 68;
    extern __shared__ char smraw[];
    float*    halo = (float*)smraw;                        // 180*68 floats
    uint32_t* Bf   = (uint32_t*)(smraw + 180 * PST * 4);   // 4 x 4096 uints

    const int x0 = blockIdx.x * 16;
    const int y0 = blockIdx.y * 8;
    const int b  = blockIdx.z;
    const int tid = threadIdx.x;
    const int warp = tid >> 5, lane = tid & 31;
    const int lr = lane >> 2, lc = lane & 3;

    // group 1: Q -> slot0
    #pragma unroll
    for (int i = 0; i < 4; i++) { int o = (tid + i * 256) * 4; cp16(Bf + o, wQ + o); }
    cp_commit();
    // group 2: K0 -> slot1, V0 -> slot2
    #pragma unroll
    for (int i = 0; i < 4; i++) { int o = (tid + i * 256) * 4; cp16(Bf + 4096 + o, wK + o); }
    #pragma unroll
    for (int i = 0; i < 4; i++) { int o = (tid + i * 256) * 4; cp16(Bf + 8192 + o, wV + o); }
    cp_commit();

    // x-halo: tf32-rounded, zero-padded
    for (int idx = tid * 4; idx < 180 * 64; idx += 1024) {
        int c = idx & 63;
        int sp = idx >> 6;
        int hy = sp / HW2, hx = sp - hy * HW2;
        int gy = y0 + hy - 1, gx = x0 + hx - 1;
        float4 v = make_float4(0.f, 0.f, 0.f, 0.f);
        if ((unsigned)gy < HH && (unsigned)gx < WW)
            v = *(const float4*)(x + (((size_t)b * HH + gy) * WW + gx) * 64 + c);
        float* d = halo + sp * PST + c;
        d[0] = tf32r(v.x); d[1] = tf32r(v.y); d[2] = tf32r(v.z); d[3] = tf32r(v.w);
    }
    cp_wait1();          // Q landed (K0/V0 may still be in flight)
    __syncthreads();     // halo + Q visible

    const int off0 = (warp * HW2 + lr) * PST;
    const int off8 = (warp * HW2 + lr + 8) * PST;

    // ---- Q GEMM (center tap offset (1,1)) ----
    float q[8][4];
    {
        const int toff = (1 * HW2 + 1) * PST;
        float acc[8][4] = {};
        gemm64(acc, Bf + lane * 2, halo + off0 + toff + lc, halo + off8 + toff + lc);
        #pragma unroll
        for (int nf = 0; nf < 8; nf++)
            #pragma unroll
            for (int j = 0; j < 4; j++) q[nf][j] = acc[nf][j];
    }

    // ---- online-softmax tap loop ----
    // v index: 0 = head0/row lr, 1 = head1/row lr, 2 = head0/row lr+8, 3 = head1/row lr+8
    float mrun[4] = {-1e30f, -1e30f, -1e30f, -1e30f};
    float denom[4] = {0.f, 0.f, 0.f, 0.f};
    float attn[8][4] = {};

    #pragma unroll
    for (int t = 0; t < NP; t++) {
        const int sK = (t & 1) ? 3 : 1;
        const int sV = (t & 1) ? 0 : 2;

        cp_wait0();          // pair t landed
        __syncthreads();     // prior stage's readers done (safe to overwrite t-1 slots)

        if (t < 8) {         // prefetch pair t+1 into the slots freed by pair t-1
            const int nK = (t & 1) ? 1 : 3;
            const int nV = (t & 1) ? 2 : 0;
            const uint32_t* srcK = wK + (t + 1) * 4096;
            const uint32_t* srcV = wV + (t + 1) * 4096;
            #pragma unroll
            for (int i = 0; i < 4; i++) { int o = (tid + i * 256) * 4; cp16(Bf + nK * 4096 + o, srcK + o); }
            #pragma unroll
            for (int i = 0; i < 4; i++) { int o = (tid + i * 256) * 4; cp16(Bf + nV * 4096 + o, srcV + o); }
            cp_commit();
        } else {             // prefetch ff1 -> slot3
            #pragma unroll
            for (int i = 0; i < 4; i++) { int o = (tid + i * 256) * 4; cp16(Bf + 3 * 4096 + o, wF1 + o); }
            cp_commit();
        }

        const int toff = ((t / 3) * HW2 + (t % 3)) * PST;
        const float* A0 = halo + off0 + toff + lc;
        const float* A8 = halo + off8 + toff + lc;

        // K_t GEMM -> scores
        float acc[8][4] = {};
        gemm64(acc, Bf + sK * 4096 + lane * 2, A0, A8);

        float p[4] = {0.f, 0.f, 0.f, 0.f};
        #pragma unroll
        for (int nf = 0; nf < 8; nf++) {
            const int hd = nf >> 2;
            p[hd]     += acc[nf][0] * q[nf][0] + acc[nf][1] * q[nf][1];
            p[2 + hd] += acc[nf][2] * q[nf][2] + acc[nf][3] * q[nf][3];
        }
        float e[4], scale[4];
        #pragma unroll
        for (int v = 0; v < 4; v++) {
            p[v] += __shfl_xor_sync(0xffffffffu, p[v], 1);
            p[v] += __shfl_xor_sync(0xffffffffu, p[v], 2);
            float s = p[v] * (1.0f / 3.0f);
            float mn = fmaxf(mrun[v], s);
            scale[v] = __expf(mrun[v] - mn);
            e[v]     = __expf(s - mn);
            denom[v] = denom[v] * scale[v] + e[v];
            mrun[v]  = mn;
        }

        // V_t GEMM -> weighted accumulate with rescale
        #pragma unroll
        for (int nf = 0; nf < 8; nf++)
            #pragma unroll
            for (int j = 0; j < 4; j++) acc[nf][j] = 0.f;
        gemm64(acc, Bf + sV * 4096 + lane * 2, A0, A8);

        #pragma unroll
        for (int nf = 0; nf < 8; nf++) {
            const int hd = nf >> 2;
            attn[nf][0] = attn[nf][0] * scale[hd]     + e[hd]     * acc[nf][0];
            attn[nf][1] = attn[nf][1] * scale[hd]     + e[hd]     * acc[nf][1];
            attn[nf][2] = attn[nf][2] * scale[2 + hd] + e[2 + hd] * acc[nf][2];
            attn[nf][3] = attn[nf][3] * scale[2 + hd] + e[2 + hd] * acc[nf][3];
        }
    }

    // normalize
    float inv[4];
    #pragma unroll
    for (int v = 0; v < 4; v++) inv[v] = 1.0f / denom[v];

    // ---- ff1 (slot3). attn -> smem (tf32) -> GEMM -> t1 ----
    cp_wait0();
    __syncthreads();     // all tap-8 reads done; halo reusable

    float* Ast = halo;
    #pragma unroll
    for (int nf = 0; nf < 8; nf++) {
        const int hd = nf >> 2;
        int col = nf * 8 + lc * 2;
        *(float2*)&Ast[(warp * 16 + lr) * PST + col] =
            make_float2(tf32r(attn[nf][0] * inv[hd]), tf32r(attn[nf][1] * inv[hd]));
        *(float2*)&Ast[(warp * 16 + lr + 8) * PST + col] =
            make_float2(tf32r(attn[nf][2] * inv[2 + hd]), tf32r(attn[nf][3] * inv[2 + hd]));
    }
    __syncthreads();

    float acc[8][4] = {};
    gemm64(acc, Bf + 3 * 4096 + lane * 2,
           Ast + (warp * 16 + lr) * PST + lc,
           Ast + (warp * 16 + lr + 8) * PST + lc);

    const int ygl = y0 + warp;
    const size_t p0 = ((size_t)b * HH + ygl) * WW + x0 + lr;
    const size_t p1 = p0 + 8;
    #pragma unroll
    for (int nf = 0; nf < 8; nf++) {
        int col = nf * 8 + lc * 2;
        float b0 = bias1[col], b1 = bias1[col + 1];
        *(float2*)(t1 + p0 * 64 + col) = make_float2(
            tf32r(fmaxf(acc[nf][0] + b0, 0.f)), tf32r(fmaxf(acc[nf][1] + b1, 0.f)));
        *(float2*)(t1 + p1 * 64 + col) = make_float2(
            tf32r(fmaxf(acc[nf][2] + b0, 0.f)), tf32r(fmaxf(acc[nf][3] + b1, 0.f)));
    }
}

// ---------------------------------------------------------------------------
// 3x3 conv, implicit GEMM (R6-proven inner loop). 8x16 tile, 128 threads,
// 64 couts per block. conv2: COUT split over gridz (SPLIT=2, CHUNKS=1).
// conv3: CIN chunked (SPLIT=1, CHUNKS=2). Full-tap double-buffered weights.
// grid = (W/16, H/8, B*SPLIT)
// ---------------------------------------------------------------------------
template <int CIN, int COUT_TOT, int SPLIT, bool ROUND>
__global__ __launch_bounds__(128, 2) void conv_tf32(
    const float* __restrict__ in, const uint32_t* __restrict__ wfrag,
    const float* __restrict__ bias, float* __restrict__ out)
{
    constexpr int HW2 = 18, PST = 68;
    constexpr int HALO_F = 10 * HW2 * PST;
    constexpr int CHUNKS = CIN / 64;
    constexpr int WTAP = 4096;
    constexpr int CPT = WTAP / 4 / 128;        // 8
    constexpr int MFS = 2;

    extern __shared__ char smraw[];
    float*    halo = (float*)smraw;
    uint32_t* Bf   = (uint32_t*)(smraw + HALO_F * 4);   // 2 x WTAP

    const int x0 = blockIdx.x * 16;
    const int y0 = blockIdx.y * 8;
    const int b  = blockIdx.z / SPLIT;
    const int cb = blockIdx.z % SPLIT;
    const int co0 = cb * 64;
    const int tid = threadIdx.x;
    const int warp = tid >> 5, lane = tid & 31;
    const int lr = lane >> 2, lc = lane & 3;

    float acc[MFS][8][4] = {};

    int pixoff[MFS][2];
    #pragma unroll
    for (int mf = 0; mf < MFS; mf++)
        #pragma unroll
        for (int r8 = 0; r8 < 2; r8++) {
            int m = warp * 32 + mf * 16 + r8 * 8 + lr;
            int py = m >> 4, px = m & 15;
            pixoff[mf][r8] = (py * HW2 + px) * PST;
        }

    for (int ch = 0; ch < CHUNKS; ch++) {
        const int cin0 = ch * 64;
        __syncthreads();   // prior chunk fully consumed

        // prime tap 0 (overlaps halo staging)
        {
            const uint32_t* src = wfrag + (size_t)(0 * CHUNKS * SPLIT + ch * SPLIT + cb) * WTAP;
            #pragma unroll
            for (int i = 0; i < CPT; i++) { int o = (tid + i * 128) * 4; cp16(Bf + o, src + o); }
            cp_commit();
        }

        for (int idx = tid * 4; idx < 10 * HW2 * 64; idx += 128 * 4) {
            int c = idx & 63;
            int sp = idx >> 6;
            int hy = sp / HW2, hx = sp - hy * HW2;
            int gy = y0 + hy - 1, gx = x0 + hx - 1;
            float4 v = make_float4(0.f, 0.f, 0.f, 0.f);
            if ((unsigned)gy < HH && (unsigned)gx < WW)
                v = *(const float4*)(in + (((size_t)b * HH + gy) * WW + gx) * CIN + cin0 + c);
            *(float4*)(halo + sp * PST + c) = v;
        }
        cp_wait0();
        __syncthreads();

        for (int t = 0; t < 9; t++) {
            if (t < 8) {
                uint32_t* nb = Bf + ((t + 1) & 1) * WTAP;
                const uint32_t* src = wfrag + (size_t)((t + 1) * CHUNKS * SPLIT + ch * SPLIT + cb) * WTAP;
                #pragma unroll
                for (int i = 0; i < CPT; i++) { int o = (tid + i * 128) * 4; cp16(nb + o, src + o); }
                cp_commit();
            }

            const uint32_t* Bc = Bf + (t & 1) * WTAP;
            const int toff = ((t / 3) * HW2 + (t % 3)) * PST;

            #pragma unroll
            for (int ks = 0; ks < 8; ks++) {
                uint32_t a[MFS][4];
                #pragma unroll
                for (int mf = 0; mf < MFS; mf++) {
                    const float* b0 = halo + pixoff[mf][0] + toff + ks * 8 + lc;
                    const float* b1 = halo + pixoff[mf][1] + toff + ks * 8 + lc;
                    a[mf][0] = __float_as_uint(b0[0]);
                    a[mf][1] = __float_as_uint(b1[0]);
                    a[mf][2] = __float_as_uint(b0[4]);
                    a[mf][3] = __float_as_uint(b1[4]);
                }
                #pragma unroll
                for (int nf = 0; nf < 8; nf++) {
                    uint2 bv = *(const uint2*)&Bc[(ks * 8 + nf) * 64 + lane * 2];
                    uint32_t br[2] = {bv.x, bv.y};
                    #pragma unroll
                    for (int mf = 0; mf < MFS; mf++)
                        mma8(acc[mf][nf], a[mf], br);
                }
            }

            if (t < 8) { cp_wait0(); __syncthreads(); }
        }
    }

    #pragma unroll
    for (int mf = 0; mf < MFS; mf++) {
        #pragma unroll
        for (int r8 = 0; r8 < 2; r8++) {
            int m = warp * 32 + mf * 16 + r8 * 8 + lr;
            int py = m >> 4, px = m & 15;
            int y = y0 + py, xx = x0 + px;
            size_t base = (((size_t)b * HH + y) * WW + xx) * COUT_TOT + co0;
            #pragma unroll
            for (int nf = 0; nf < 8; nf++) {
                int n = nf * 8 + lc * 2;
                float vx = fmaxf(acc[mf][nf][r8 * 2 + 0] + bias[co0 + n], 0.f);
                float vy = fmaxf(acc[mf][nf][r8 * 2 + 1] + bias[co0 + n + 1], 0.f);
                if (ROUND) { vx = tf32r(vx); vy = tf32r(vy); }
                *(float2*)(out + base + n) = make_float2(vx, vy);
            }
        }
    }
}

// ---------------------------------------------------------------------------
// Launch
// ---------------------------------------------------------------------------
extern "C" void kernel_launch(void* const* d_in, const int* in_sizes, int n_in,
                              void* d_out, int out_size)
{
    const float* x      = (const float*)d_in[0];
    const float* K_P    = (const float*)d_in[1];
    const float* V_P    = (const float*)d_in[2];
    const float* Q_P    = (const float*)d_in[3];
    const float* ff1_k  = (const float*)d_in[4];
    const float* ff1_b  = (const float*)d_in[5];
    const float* ff2_k  = (const float*)d_in[6];
    const float* ff2_b  = (const float*)d_in[7];
    const float* ff3_k  = (const float*)d_in[8];
    const float* ff3_b  = (const float*)d_in[9];
    float* out = (float*)d_out;

    float *t1, *t2;
    uint32_t *wKf, *wVf, *wQf, *wF1f, *wc2f, *wc3f;
    cudaGetSymbolAddress((void**)&t1,   g_t1);
    cudaGetSymbolAddress((void**)&t2,   g_t2);
    cudaGetSymbolAddress((void**)&wKf,  g_wKf);
    cudaGetSymbolAddress((void**)&wVf,  g_wVf);
    cudaGetSymbolAddress((void**)&wQf,  g_wQf);
    cudaGetSymbolAddress((void**)&wF1f, g_wF1f);
    cudaGetSymbolAddress((void**)&wc2f, g_wc2f);
    cudaGetSymbolAddress((void**)&wc3f, g_wc3f);

    const int FUSED_SMEM = 180 * 68 * 4 + 4 * 4096 * 4;    // 114496
    const int CONV_SMEM  = 180 * 68 * 4 + 2 * 4096 * 4;    // 81728

    cudaFuncSetAttribute(attn_fused, cudaFuncAttributeMaxDynamicSharedMemorySize, FUSED_SMEM);
    cudaFuncSetAttribute((conv_tf32<64, 128, 2, true>),  cudaFuncAttributeMaxDynamicSharedMemorySize, CONV_SMEM);
    cudaFuncSetAttribute((conv_tf32<128, 64, 1, false>), cudaFuncAttributeMaxDynamicSharedMemorySize, CONV_SMEM);

    prep_w<<<896, 256>>>(K_P, V_P, Q_P, ff1_k, ff2_k, ff3_k);

    // Fused projections + online-softmax attention + ff1
    attn_fused<<<dim3(WW / 16, HH / 8, BB), 256, FUSED_SMEM>>>(
        x, wQf, wKf, wVf, wF1f, ff1_b, t1);

    // Convs
    conv_tf32<64, 128, 2, true><<<dim3(WW / 16, HH / 8, BB * 2), 128, CONV_SMEM>>>(t1, wc2f, ff2_b, t2);
    conv_tf32<128, 64, 1, false><<<dim3(WW / 16, HH / 8, BB), 128, CONV_SMEM>>>(t2, wc3f, ff3_b, out);
}

// round 9
// speedup vs baseline: 1.5576x; 1.3593x over previous
#include <cuda_runtime.h>
#include <cuda_fp16.h>
#include <cstdint>
#include <cstddef>

#define BB 4
#define HH 128
#define WW 128
#define NP 9
#define PTOT (BB*HH*WW)

// ---------------------------------------------------------------------------
// Scratch
// ---------------------------------------------------------------------------
__device__ float  g_t1 [(size_t)PTOT * 64];     // tf32-rounded fp32
__device__ __half g_t2 [(size_t)PTOT * 128];    // fp16
// attn weights: gemm-style tf32 tiles
__device__ uint32_t g_wKf[9 * 4096];
__device__ uint32_t g_wVf[9 * 4096];
__device__ uint32_t g_wQf[4096];
__device__ uint32_t g_wF1f[4096];
// conv weights: fp16, thread-major packed m16n8k16 fragments, 2048 uints/tile
__device__ __half g_wc2h[18 * 4096];            // [t*2+cb][(ks16*8+nf)*64 + lane*2 + reg][half]
__device__ __half g_wc3h[18 * 4096];            // [t*2+ch][...]

// ---------------------------------------------------------------------------
// helpers
// ---------------------------------------------------------------------------
__device__ __forceinline__ uint32_t tf32b(float x) {
    uint32_t u;
    asm("cvt.rna.tf32.f32 %0, %1;" : "=r"(u) : "f"(x));
    return u;
}
__device__ __forceinline__ float tf32r(float x) { return __uint_as_float(tf32b(x)); }

__device__ __forceinline__ void mma8(float* c, const uint32_t* a, const uint32_t* b) {
    asm volatile(
        "mma.sync.aligned.m16n8k8.row.col.f32.tf32.tf32.f32 "
        "{%0,%1,%2,%3}, {%4,%5,%6,%7}, {%8,%9}, {%0,%1,%2,%3};"
        : "+f"(c[0]), "+f"(c[1]), "+f"(c[2]), "+f"(c[3])
        : "r"(a[0]), "r"(a[1]), "r"(a[2]), "r"(a[3]),
          "r"(b[0]), "r"(b[1]));
}

__device__ __forceinline__ void mma16h(float* c, const uint32_t* a, uint2 b) {
    asm volatile(
        "mma.sync.aligned.m16n8k16.row.col.f32.f16.f16.f32 "
        "{%0,%1,%2,%3}, {%4,%5,%6,%7}, {%8,%9}, {%0,%1,%2,%3};"
        : "+f"(c[0]), "+f"(c[1]), "+f"(c[2]), "+f"(c[3])
        : "r"(a[0]), "r"(a[1]), "r"(a[2]), "r"(a[3]),
          "r"(b.x), "r"(b.y));
}

__device__ __forceinline__ void cp16(void* dst_smem, const void* src) {
    uint32_t d = (uint32_t)__cvta_generic_to_shared(dst_smem);
    asm volatile("cp.async.cg.shared.global [%0], [%1], 16;" :: "r"(d), "l"(src) : "memory");
}
__device__ __forceinline__ void cp_commit() { asm volatile("cp.async.commit_group;" ::: "memory"); }
__device__ __forceinline__ void cp_wait0()  { asm volatile("cp.async.wait_group 0;"  ::: "memory"); }
__device__ __forceinline__ void cp_wait1()  { asm volatile("cp.async.wait_group 1;"  ::: "memory"); }

// gemm-style 64-wide warp step (attn_fused)
__device__ __forceinline__ void gemm64(float (&acc)[8][4], const uint32_t* Bl,
                                       const float* A0, const float* A8)
{
    #pragma unroll
    for (int ks = 0; ks < 8; ks++) {
        uint32_t a[4];
        a[0] = __float_as_uint(A0[ks * 8]);
        a[1] = __float_as_uint(A8[ks * 8]);
        a[2] = __float_as_uint(A0[ks * 8 + 4]);
        a[3] = __float_as_uint(A8[ks * 8 + 4]);
        #pragma unroll
        for (int nf = 0; nf < 8; nf++) {
            uint2 bv = *(const uint2*)&Bl[(ks * 8 + nf) * 64];
            uint32_t br[2] = {bv.x, bv.y};
            mma8(acc[nf], a, br);
        }
    }
}

// ---------------------------------------------------------------------------
// Prep: attn weights -> tf32 gemm-style; conv weights -> fp16 packed frags
// ---------------------------------------------------------------------------
__global__ __launch_bounds__(256) void prep_w(
    const float* __restrict__ K_P, const float* __restrict__ V_P,
    const float* __restrict__ Q_P, const float* __restrict__ F1,
    const float* __restrict__ W2, const float* __restrict__ W3)
{
    int i = blockIdx.x * 256 + threadIdx.x;
    if (i < 73728) {                               // K_P / V_P [64,576]
        const float* src = (i < 36864) ? K_P : V_P;
        uint32_t* dst = (i < 36864) ? g_wKf : g_wVf;
        int j = (i < 36864) ? i : i - 36864;
        int k = j / 576, n = j % 576;
        int nt = n >> 6, nl = n & 63;
        int pos = ((k >> 3) * 8 + (nl >> 3)) * 64 + (((nl & 7) << 2) | (k & 3)) * 2 + ((k & 7) >> 2);
        dst[nt * 4096 + pos] = tf32b(src[j]);
    } else if (i < 81920) {                        // Q_P / ff1 [64,64]
        int j = i - 73728;
        const float* src = (j < 4096) ? Q_P : F1;
        uint32_t* dst = (j < 4096) ? g_wQf : g_wF1f;
        int jj = j & 4095;
        int k = jj >> 6, n = jj & 63;
        int pos = ((k >> 3) * 8 + (n >> 3)) * 64 + (((n & 7) << 2) | (k & 3)) * 2 + ((k & 7) >> 2);
        dst[pos] = tf32b(src[jj]);
    } else if (i < 155648) {                       // ff2 [9][64][128] -> fp16 COUT-split tiles
        int j = i - 81920;
        int t = j >> 13, k = (j >> 7) & 63, n = j & 127;
        int cb = n >> 6, nl = n & 63;
        int ks16 = k >> 4, kl = k & 15;
        int nf = nl >> 3, colf = nl & 7;
        int krel = kl & 7, reg = kl >> 3;
        int lane = colf * 4 + (krel >> 1);
        size_t hidx = ((size_t)(t * 2 + cb) * 2048 + (ks16 * 8 + nf) * 64 + lane * 2 + reg) * 2 + (krel & 1);
        g_wc2h[hidx] = __float2half_rn(W2[j]);
    } else {                                       // ff3 [9][128][64] -> fp16 CIN-chunk tiles
        int j = i - 155648;
        int t = j >> 13, k = (j >> 6) & 127, n = j & 63;
        int ch = k >> 6, kl = k & 63;
        int ks16 = kl >> 4, kk = kl & 15;
        int nf = n >> 3, colf = n & 7;
        int krel = kk & 7, reg = kk >> 3;
        int lane = colf * 4 + (krel >> 1);
        size_t hidx = ((size_t)(t * 2 + ch) * 2048 + (ks16 * 8 + nf) * 64 + lane * 2 + reg) * 2 + (krel & 1);
        g_wc3h[hidx] = __float2half_rn(W3[j]);
    }
}

// ---------------------------------------------------------------------------
// Fused attention with online softmax + ff1 (unchanged from R8).
// ---------------------------------------------------------------------------
__global__ __launch_bounds__(256) void attn_fused(
    const float* __restrict__ x,
    const uint32_t* __restrict__ wQ, const uint32_t* __restrict__ wK,
    const uint32_t* __restrict__ wV, const uint32_t* __restrict__ wF1,
    const float* __restrict__ bias1, float* __restrict__ t1)
{
    constexpr int HW2 = 18, PST = 68;
    extern __shared__ char smraw[];
    float*    halo = (float*)smraw;                        // 180*68 floats
    uint32_t* Bf   = (uint32_t*)(smraw + 180 * PST * 4);   // 4 x 4096 uints

    const int x0 = blockIdx.x * 16;
    const int y0 = blockIdx.y * 8;
    const int b  = blockIdx.z;
    const int tid = threadIdx.x;
    const int warp = tid >> 5, lane = tid & 31;
    const int lr = lane >> 2, lc = lane & 3;

    #pragma unroll
    for (int i = 0; i < 4; i++) { int o = (tid + i * 256) * 4; cp16(Bf + o, wQ + o); }
    cp_commit();
    #pragma unroll
    for (int i = 0; i < 4; i++) { int o = (tid + i * 256) * 4; cp16(Bf + 4096 + o, wK + o); }
    #pragma unroll
    for (int i = 0; i < 4; i++) { int o = (tid + i * 256) * 4; cp16(Bf + 8192 + o, wV + o); }
    cp_commit();

    for (int idx = tid * 4; idx < 180 * 64; idx += 1024) {
        int c = idx & 63;
        int sp = idx >> 6;
        int hy = sp / HW2, hx = sp - hy * HW2;
        int gy = y0 + hy - 1, gx = x0 + hx - 1;
        float4 v = make_float4(0.f, 0.f, 0.f, 0.f);
        if ((unsigned)gy < HH && (unsigned)gx < WW)
            v = *(const float4*)(x + (((size_t)b * HH + gy) * WW + gx) * 64 + c);
        float* d = halo + sp * PST + c;
        d[0] = tf32r(v.x); d[1] = tf32r(v.y); d[2] = tf32r(v.z); d[3] = tf32r(v.w);
    }
    cp_wait1();
    __syncthreads();

    const int off0 = (warp * HW2 + lr) * PST;
    const int off8 = (warp * HW2 + lr + 8) * PST;

    float q[8][4];
    {
        const int toff = (1 * HW2 + 1) * PST;
        float acc[8][4] = {};
        gemm64(acc, Bf + lane * 2, halo + off0 + toff + lc, halo + off8 + toff + lc);
        #pragma unroll
        for (int nf = 0; nf < 8; nf++)
            #pragma unroll
            for (int j = 0; j < 4; j++) q[nf][j] = acc[nf][j];
    }

    float mrun[4] = {-1e30f, -1e30f, -1e30f, -1e30f};
    float denom[4] = {0.f, 0.f, 0.f, 0.f};
    float attn[8][4] = {};

    #pragma unroll
    for (int t = 0; t < NP; t++) {
        const int sK = (t & 1) ? 3 : 1;
        const int sV = (t & 1) ? 0 : 2;

        cp_wait0();
        __syncthreads();

        if (t < 8) {
            const int nK = (t & 1) ? 1 : 3;
            const int nV = (t & 1) ? 2 : 0;
            const uint32_t* srcK = wK + (t + 1) * 4096;
            const uint32_t* srcV = wV + (t + 1) * 4096;
            #pragma unroll
            for (int i = 0; i < 4; i++) { int o = (tid + i * 256) * 4; cp16(Bf + nK * 4096 + o, srcK + o); }
            #pragma unroll
            for (int i = 0; i < 4; i++) { int o = (tid + i * 256) * 4; cp16(Bf + nV * 4096 + o, srcV + o); }
            cp_commit();
        } else {
            #pragma unroll
            for (int i = 0; i < 4; i++) { int o = (tid + i * 256) * 4; cp16(Bf + 3 * 4096 + o, wF1 + o); }
            cp_commit();
        }

        const int toff = ((t / 3) * HW2 + (t % 3)) * PST;
        const float* A0 = halo + off0 + toff + lc;
        const float* A8 = halo + off8 + toff + lc;

        float acc[8][4] = {};
        gemm64(acc, Bf + sK * 4096 + lane * 2, A0, A8);

        float p[4] = {0.f, 0.f, 0.f, 0.f};
        #pragma unroll
        for (int nf = 0; nf < 8; nf++) {
            const int hd = nf >> 2;
            p[hd]     += acc[nf][0] * q[nf][0] + acc[nf][1] * q[nf][1];
            p[2 + hd] += acc[nf][2] * q[nf][2] + acc[nf][3] * q[nf][3];
        }
        float e[4], scale[4];
        #pragma unroll
        for (int v = 0; v < 4; v++) {
            p[v] += __shfl_xor_sync(0xffffffffu, p[v], 1);
            p[v] += __shfl_xor_sync(0xffffffffu, p[v], 2);
            float s = p[v] * (1.0f / 3.0f);
            float mn = fmaxf(mrun[v], s);
            scale[v] = __expf(mrun[v] - mn);
            e[v]     = __expf(s - mn);
            denom[v] = denom[v] * scale[v] + e[v];
            mrun[v]  = mn;
        }

        #pragma unroll
        for (int nf = 0; nf < 8; nf++)
            #pragma unroll
            for (int j = 0; j < 4; j++) acc[nf][j] = 0.f;
        gemm64(acc, Bf + sV * 4096 + lane * 2, A0, A8);

        #pragma unroll
        for (int nf = 0; nf < 8; nf++) {
            const int hd = nf >> 2;
            attn[nf][0] = attn[nf][0] * scale[hd]     + e[hd]     * acc[nf][0];
            attn[nf][1] = attn[nf][1] * scale[hd]     + e[hd]     * acc[nf][1];
            attn[nf][2] = attn[nf][2] * scale[2 + hd] + e[2 + hd] * acc[nf][2];
            attn[nf][3] = attn[nf][3] * scale[2 + hd] + e[2 + hd] * acc[nf][3];
        }
    }

    float inv[4];
    #pragma unroll
    for (int v = 0; v < 4; v++) inv[v] = 1.0f / denom[v];

    cp_wait0();
    __syncthreads();

    float* Ast = halo;
    #pragma unroll
    for (int nf = 0; nf < 8; nf++) {
        const int hd = nf >> 2;
        int col = nf * 8 + lc * 2;
        *(float2*)&Ast[(warp * 16 + lr) * PST + col] =
            make_float2(tf32r(attn[nf][0] * inv[hd]), tf32r(attn[nf][1] * inv[hd]));
        *(float2*)&Ast[(warp * 16 + lr + 8) * PST + col] =
            make_float2(tf32r(attn[nf][2] * inv[2 + hd]), tf32r(attn[nf][3] * inv[2 + hd]));
    }
    __syncthreads();

    float acc[8][4] = {};
    gemm64(acc, Bf + 3 * 4096 + lane * 2,
           Ast + (warp * 16 + lr) * PST + lc,
           Ast + (warp * 16 + lr + 8) * PST + lc);

    const int ygl = y0 + warp;
    const size_t p0 = ((size_t)b * HH + ygl) * WW + x0 + lr;
    const size_t p1 = p0 + 8;
    #pragma unroll
    for (int nf = 0; nf < 8; nf++) {
        int col = nf * 8 + lc * 2;
        float b0 = bias1[col], b1 = bias1[col + 1];
        *(float2*)(t1 + p0 * 64 + col) = make_float2(
            tf32r(fmaxf(acc[nf][0] + b0, 0.f)), tf32r(fmaxf(acc[nf][1] + b1, 0.f)));
        *(float2*)(t1 + p1 * 64 + col) = make_float2(
            tf32r(fmaxf(acc[nf][2] + b0, 0.f)), tf32r(fmaxf(acc[nf][3] + b1, 0.f)));
    }
}

// ---------------------------------------------------------------------------
// fp16 3x3 conv, implicit GEMM with m16n8k16 (fp32 accumulate).
// 8x16 tile, 128 threads, 64 couts/block. Halo fp16 stride 72 (36 words
// = 4 mod 32 -> conflict-free A LDS). Weights fp16 packed thread-major.
// IN_HALF: input tensor dtype. OUT_HALF: store fp16 (t2) vs fp32 (final).
// grid = (W/16, H/8, B*SPLIT)
// ---------------------------------------------------------------------------
template <bool IN_HALF, int CIN, int COUT_TOT, int SPLIT, bool OUT_HALF>
__global__ __launch_bounds__(128, 3) void conv_fp16(
    const void* __restrict__ in_, const uint32_t* __restrict__ wfrag,
    const float* __restrict__ bias, void* __restrict__ out_)
{
    constexpr int HW2 = 18, PSTH = 72;          // halves per halo row
    constexpr int HALO_H = 10 * HW2 * PSTH;     // 12960 halves
    constexpr int CHUNKS = CIN / 64;
    constexpr int WTAP = 2048;                  // uints per tile
    constexpr int CPT = WTAP / 4 / 128;         // 4 cp16/thread
    constexpr int MFS = 2;

    extern __shared__ char smraw[];
    __half*   haloH = (__half*)smraw;
    uint32_t* Bf    = (uint32_t*)(smraw + HALO_H * 2);  // 2 x WTAP

    const int x0 = blockIdx.x * 16;
    const int y0 = blockIdx.y * 8;
    const int b  = blockIdx.z / SPLIT;
    const int cb = blockIdx.z % SPLIT;
    const int co0 = cb * 64;
    const int tid = threadIdx.x;
    const int warp = tid >> 5, lane = tid & 31;
    const int lr = lane >> 2, lc = lane & 3;

    float acc[MFS][8][4] = {};

    int pixoff[MFS][2];
    #pragma unroll
    for (int mf = 0; mf < MFS; mf++)
        #pragma unroll
        for (int r8 = 0; r8 < 2; r8++) {
            int m = warp * 32 + mf * 16 + r8 * 8 + lr;
            int py = m >> 4, px = m & 15;
            pixoff[mf][r8] = (py * HW2 + px) * PSTH;
        }

    for (int ch = 0; ch < CHUNKS; ch++) {
        const int cin0 = ch * 64;
        __syncthreads();   // prior chunk fully consumed

        // prime tap 0 weights (overlaps halo staging)
        {
            const uint32_t* src = wfrag + (size_t)(0 * CHUNKS * SPLIT + ch * SPLIT + cb) * WTAP;
            #pragma unroll
            for (int i = 0; i < CPT; i++) { int o = (tid + i * 128) * 4; cp16(Bf + o, src + o); }
            cp_commit();
        }

        // halo staging
        if (IN_HALF) {
            const __half* in = (const __half*)in_;
            for (int idx = tid * 8; idx < 10 * HW2 * 64; idx += 128 * 8) {
                int c = idx & 63;
                int sp = idx >> 6;
                int hy = sp / HW2, hx = sp - hy * HW2;
                int gy = y0 + hy - 1, gx = x0 + hx - 1;
                uint4 v = make_uint4(0u, 0u, 0u, 0u);
                if ((unsigned)gy < HH && (unsigned)gx < WW)
                    v = *(const uint4*)(in + (((size_t)b * HH + gy) * WW + gx) * CIN + cin0 + c);
                *(uint4*)(haloH + sp * PSTH + c) = v;
            }
        } else {
            const float* in = (const float*)in_;
            for (int idx = tid * 4; idx < 10 * HW2 * 64; idx += 128 * 4) {
                int c = idx & 63;
                int sp = idx >> 6;
                int hy = sp / HW2, hx = sp - hy * HW2;
                int gy = y0 + hy - 1, gx = x0 + hx - 1;
                float4 v = make_float4(0.f, 0.f, 0.f, 0.f);
                if ((unsigned)gy < HH && (unsigned)gx < WW)
                    v = *(const float4*)(in + (((size_t)b * HH + gy) * WW + gx) * CIN + cin0 + c);
                __half2 h01 = __floats2half2_rn(v.x, v.y);
                __half2 h23 = __floats2half2_rn(v.z, v.w);
                *(uint2*)(haloH + sp * PSTH + c) =
                    make_uint2(*(uint32_t*)&h01, *(uint32_t*)&h23);
            }
        }
        cp_wait0();
        __syncthreads();

        for (int t = 0; t < 9; t++) {
            if (t < 8) {
                uint32_t* nb = Bf + ((t + 1) & 1) * WTAP;
                const uint32_t* src = wfrag + (size_t)((t + 1) * CHUNKS * SPLIT + ch * SPLIT + cb) * WTAP;
                #pragma unroll
                for (int i = 0; i < CPT; i++) { int o = (tid + i * 128) * 4; cp16(nb + o, src + o); }
                cp_commit();
            }

            const uint32_t* Bc = Bf + (t & 1) * WTAP;
            const int toff = ((t / 3) * HW2 + (t % 3)) * PSTH;

            #pragma unroll
            for (int ks16 = 0; ks16 < 4; ks16++) {
                uint32_t a[MFS][4];
                #pragma unroll
                for (int mf = 0; mf < MFS; mf++) {
                    const __half* b0 = haloH + pixoff[mf][0] + toff + ks16 * 16 + 2 * lc;
                    const __half* b1 = haloH + pixoff[mf][1] + toff + ks16 * 16 + 2 * lc;
                    a[mf][0] = *(const uint32_t*)b0;
                    a[mf][1] = *(const uint32_t*)b1;
                    a[mf][2] = *(const uint32_t*)(b0 + 8);
                    a[mf][3] = *(const uint32_t*)(b1 + 8);
                }
                #pragma unroll
                for (int nf = 0; nf < 8; nf++) {
                    uint2 bv = *(const uint2*)&Bc[(ks16 * 8 + nf) * 64 + lane * 2];
                    #pragma unroll
                    for (int mf = 0; mf < MFS; mf++)
                        mma16h(acc[mf][nf], a[mf], bv);
                }
            }

            if (t < 8) { cp_wait0(); __syncthreads(); }
        }
    }

    // epilogue: bias + relu
    #pragma unroll
    for (int mf = 0; mf < MFS; mf++) {
        #pragma unroll
        for (int r8 = 0; r8 < 2; r8++) {
            int m = warp * 32 + mf * 16 + r8 * 8 + lr;
            int py = m >> 4, px = m & 15;
            int y = y0 + py, xx = x0 + px;
            size_t base = (((size_t)b * HH + y) * WW + xx) * COUT_TOT + co0;
            #pragma unroll
            for (int nf = 0; nf < 8; nf++) {
                int n = nf * 8 + lc * 2;
                float vx = fmaxf(acc[mf][nf][r8 * 2 + 0] + bias[co0 + n], 0.f);
                float vy = fmaxf(acc[mf][nf][r8 * 2 + 1] + bias[co0 + n + 1], 0.f);
                if (OUT_HALF) {
                    __half2 h = __floats2half2_rn(vx, vy);
                    *(__half2*)((__half*)out_ + base + n) = h;
                } else {
                    *(float2*)((float*)out_ + base + n) = make_float2(vx, vy);
                }
            }
        }
    }
}

// ---------------------------------------------------------------------------
// Launch
// ---------------------------------------------------------------------------
extern "C" void kernel_launch(void* const* d_in, const int* in_sizes, int n_in,
                              void* d_out, int out_size)
{
    const float* x      = (const float*)d_in[0];
    const float* K_P    = (const float*)d_in[1];
    const float* V_P    = (const float*)d_in[2];
    const float* Q_P    = (const float*)d_in[3];
    const float* ff1_k  = (const float*)d_in[4];
    const float* ff1_b  = (const float*)d_in[5];
    const float* ff2_k  = (const float*)d_in[6];
    const float* ff2_b  = (const float*)d_in[7];
    const float* ff3_k  = (const float*)d_in[8];
    const float* ff3_b  = (const float*)d_in[9];
    float* out = (float*)d_out;

    float *t1;
    __half *t2, *wc2h, *wc3h;
    uint32_t *wKf, *wVf, *wQf, *wF1f;
    cudaGetSymbolAddress((void**)&t1,   g_t1);
    cudaGetSymbolAddress((void**)&t2,   g_t2);
    cudaGetSymbolAddress((void**)&wKf,  g_wKf);
    cudaGetSymbolAddress((void**)&wVf,  g_wVf);
    cudaGetSymbolAddress((void**)&wQf,  g_wQf);
    cudaGetSymbolAddress((void**)&wF1f, g_wF1f);
    cudaGetSymbolAddress((void**)&wc2h, g_wc2h);
    cudaGetSymbolAddress((void**)&wc3h, g_wc3h);

    const int FUSED_SMEM = 180 * 68 * 4 + 4 * 4096 * 4;      // 114496
    const int CONV_SMEM  = 180 * 72 * 2 + 2 * 2048 * 4;      // 42304

    cudaFuncSetAttribute(attn_fused, cudaFuncAttributeMaxDynamicSharedMemorySize, FUSED_SMEM);
    cudaFuncSetAttribute((conv_fp16<false, 64, 128, 2, true>), cudaFuncAttributeMaxDynamicSharedMemorySize, CONV_SMEM);
    cudaFuncSetAttribute((conv_fp16<true, 128, 64, 1, false>), cudaFuncAttributeMaxDynamicSharedMemorySize, CONV_SMEM);

    prep_w<<<896, 256>>>(K_P, V_P, Q_P, ff1_k, ff2_k, ff3_k);

    // Fused projections + online-softmax attention + ff1
    attn_fused<<<dim3(WW / 16, HH / 8, BB), 256, FUSED_SMEM>>>(
        x, wQf, wKf, wVf, wF1f, ff1_b, t1);

    // fp16 convs
    conv_fp16<false, 64, 128, 2, true><<<dim3(WW / 16, HH / 8, BB * 2), 128, CONV_SMEM>>>(
        t1, (const uint32_t*)wc2h, ff2_b, t2);
    conv_fp16<true, 128, 64, 1, false><<<dim3(WW / 16, HH / 8, BB), 128, CONV_SMEM>>>(
        t2, (const uint32_t*)wc3h, ff3_b, out);
}

// round 10
// speedup vs baseline: 1.9274x; 1.2375x over previous
#include <cuda_runtime.h>
#include <cuda_fp16.h>
#include <cstdint>
#include <cstddef>

#define BB 4
#define HH 128
#define WW 128
#define NP 9
#define PTOT (BB*HH*WW)

// ---------------------------------------------------------------------------
// Scratch
// ---------------------------------------------------------------------------
__device__ __half g_t1 [(size_t)PTOT * 64];     // fp16
__device__ __half g_t2 [(size_t)PTOT * 128];    // fp16
// all weights fp16, thread-major packed m16n8k16 fragments (4096 halves/tile)
__device__ __half g_wKh[9 * 4096];
__device__ __half g_wVh[9 * 4096];
__device__ __half g_wQh[4096];
__device__ __half g_wF1h[4096];
__device__ __half g_wc2h[18 * 4096];            // [t*2+cb]
__device__ __half g_wc3h[18 * 4096];            // [t*2+ch]

// ---------------------------------------------------------------------------
// helpers
// ---------------------------------------------------------------------------
__device__ __forceinline__ void mma16h(float* c, const uint32_t* a, uint2 b) {
    asm volatile(
        "mma.sync.aligned.m16n8k16.row.col.f32.f16.f16.f32 "
        "{%0,%1,%2,%3}, {%4,%5,%6,%7}, {%8,%9}, {%0,%1,%2,%3};"
        : "+f"(c[0]), "+f"(c[1]), "+f"(c[2]), "+f"(c[3])
        : "r"(a[0]), "r"(a[1]), "r"(a[2]), "r"(a[3]),
          "r"(b.x), "r"(b.y));
}

__device__ __forceinline__ void cp16(void* dst_smem, const void* src) {
    uint32_t d = (uint32_t)__cvta_generic_to_shared(dst_smem);
    asm volatile("cp.async.cg.shared.global [%0], [%1], 16;" :: "r"(d), "l"(src) : "memory");
}
__device__ __forceinline__ void cp_commit() { asm volatile("cp.async.commit_group;" ::: "memory"); }
__device__ __forceinline__ void cp_wait0()  { asm volatile("cp.async.wait_group 0;"  ::: "memory"); }
__device__ __forceinline__ void cp_wait1()  { asm volatile("cp.async.wait_group 1;"  ::: "memory"); }

// fp16 64-wide warp step: m-frag 16 rows, 8 n-frags, K=64 via 4 k16 steps.
// A0/A8: fp16 smem row pointers (rows lr, lr+8), already offset by +2*lc.
// Bl: packed fragment base + lane*2.
__device__ __forceinline__ void gemm64h(float (&acc)[8][4], const uint32_t* Bl,
                                        const __half* A0, const __half* A8)
{
    #pragma unroll
    for (int ks16 = 0; ks16 < 4; ks16++) {
        uint32_t a[4];
        a[0] = *(const uint32_t*)(A0 + ks16 * 16);
        a[1] = *(const uint32_t*)(A8 + ks16 * 16);
        a[2] = *(const uint32_t*)(A0 + ks16 * 16 + 8);
        a[3] = *(const uint32_t*)(A8 + ks16 * 16 + 8);
        #pragma unroll
        for (int nf = 0; nf < 8; nf++) {
            uint2 bv = *(const uint2*)&Bl[(ks16 * 8 + nf) * 64];
            mma16h(acc[nf], a, bv);
        }
    }
}

// pack position (in halves, within a 64x64 tile) for weight element (k, n)
__device__ __forceinline__ size_t packpos(int k, int n) {
    int ks16 = k >> 4, kl = k & 15;
    int nf = n >> 3, colf = n & 7;
    int krel = kl & 7, reg = kl >> 3;
    int lane = colf * 4 + (krel >> 1);
    return (size_t)(((ks16 * 8 + nf) * 64 + lane * 2 + reg) * 2 + (krel & 1));
}

// ---------------------------------------------------------------------------
// Prep: all weights -> fp16 packed fragment tiles
// ---------------------------------------------------------------------------
__global__ __launch_bounds__(256) void prep_w(
    const float* __restrict__ K_P, const float* __restrict__ V_P,
    const float* __restrict__ Q_P, const float* __restrict__ F1,
    const float* __restrict__ W2, const float* __restrict__ W3)
{
    int i = blockIdx.x * 256 + threadIdx.x;
    if (i < 73728) {                               // K_P / V_P [64,576]
        const float* src = (i < 36864) ? K_P : V_P;
        __half* dst = (i < 36864) ? g_wKh : g_wVh;
        int j = (i < 36864) ? i : i - 36864;
        int k = j / 576, n = j % 576;
        int nt = n >> 6, nl = n & 63;
        dst[(size_t)nt * 4096 + packpos(k, nl)] = __float2half_rn(src[j]);
    } else if (i < 81920) {                        // Q_P / ff1 [64,64]
        int j = i - 73728;
        const float* src = (j < 4096) ? Q_P : F1;
        __half* dst = (j < 4096) ? g_wQh : g_wF1h;
        int jj = j & 4095;
        int k = jj >> 6, n = jj & 63;
        dst[packpos(k, n)] = __float2half_rn(src[jj]);
    } else if (i < 155648) {                       // ff2 [9][64][128] -> COUT-split
        int j = i - 81920;
        int t = j >> 13, k = (j >> 7) & 63, n = j & 127;
        int cb = n >> 6, nl = n & 63;
        g_wc2h[(size_t)(t * 2 + cb) * 4096 + packpos(k, nl)] = __float2half_rn(W2[j]);
    } else {                                       // ff3 [9][128][64] -> CIN-chunked
        int j = i - 155648;
        int t = j >> 13, k = (j >> 6) & 127, n = j & 63;
        int ch = k >> 6, kl = k & 63;
        g_wc3h[(size_t)(t * 2 + ch) * 4096 + packpos(kl, n)] = __float2half_rn(W3[j]);
    }
}

// ---------------------------------------------------------------------------
// Fused fp16 attention with online softmax + ff1.
// halo fp16 stride 72 (conflict-free, conv-proven). 4 x 8KB weight slots.
// Scores / softmax / rescale / accumulators all fp32.
// ---------------------------------------------------------------------------
__global__ __launch_bounds__(256) void attn_fused(
    const float* __restrict__ x,
    const uint32_t* __restrict__ wQ, const uint32_t* __restrict__ wK,
    const uint32_t* __restrict__ wV, const uint32_t* __restrict__ wF1,
    const float* __restrict__ bias1, __half* __restrict__ t1)
{
    constexpr int HW2 = 18, PSTH = 72;
    extern __shared__ char smraw[];
    __half*   haloH = (__half*)smraw;                      // 180*72 halves
    uint32_t* Bf    = (uint32_t*)(smraw + 180 * PSTH * 2); // 4 x 2048 uints

    const int x0 = blockIdx.x * 16;
    const int y0 = blockIdx.y * 8;
    const int b  = blockIdx.z;
    const int tid = threadIdx.x;
    const int warp = tid >> 5, lane = tid & 31;
    const int lr = lane >> 2, lc = lane & 3;

    // group 1: Q -> slot0
    #pragma unroll
    for (int i = 0; i < 2; i++) { int o = (tid + i * 256) * 4; cp16(Bf + o, wQ + o); }
    cp_commit();
    // group 2: K0 -> slot1, V0 -> slot2
    #pragma unroll
    for (int i = 0; i < 2; i++) { int o = (tid + i * 256) * 4; cp16(Bf + 2048 + o, wK + o); }
    #pragma unroll
    for (int i = 0; i < 2; i++) { int o = (tid + i * 256) * 4; cp16(Bf + 4096 + o, wV + o); }
    cp_commit();

    // x-halo: fp16, zero-padded
    for (int idx = tid * 4; idx < 180 * 64; idx += 1024) {
        int c = idx & 63;
        int sp = idx >> 6;
        int hy = sp / HW2, hx = sp - hy * HW2;
        int gy = y0 + hy - 1, gx = x0 + hx - 1;
        float4 v = make_float4(0.f, 0.f, 0.f, 0.f);
        if ((unsigned)gy < HH && (unsigned)gx < WW)
            v = *(const float4*)(x + (((size_t)b * HH + gy) * WW + gx) * 64 + c);
        __half2 h01 = __floats2half2_rn(v.x, v.y);
        __half2 h23 = __floats2half2_rn(v.z, v.w);
        *(uint2*)(haloH + sp * PSTH + c) = make_uint2(*(uint32_t*)&h01, *(uint32_t*)&h23);
    }
    cp_wait1();          // Q landed
    __syncthreads();     // halo + Q visible

    const int off0 = (warp * HW2 + lr) * PSTH + 2 * lc;
    const int off8 = (warp * HW2 + lr + 8) * PSTH + 2 * lc;

    // ---- Q GEMM (center tap offset (1,1)) ----
    float q[8][4];
    {
        const int toff = (1 * HW2 + 1) * PSTH;
        float acc[8][4] = {};
        gemm64h(acc, Bf + lane * 2, haloH + off0 + toff, haloH + off8 + toff);
        #pragma unroll
        for (int nf = 0; nf < 8; nf++)
            #pragma unroll
            for (int j = 0; j < 4; j++) q[nf][j] = acc[nf][j];
    }

    // ---- online-softmax tap loop ----
    float mrun[4] = {-1e30f, -1e30f, -1e30f, -1e30f};
    float denom[4] = {0.f, 0.f, 0.f, 0.f};
    float attn[8][4] = {};

    #pragma unroll
    for (int t = 0; t < NP; t++) {
        const int sK = (t & 1) ? 3 : 1;
        const int sV = (t & 1) ? 0 : 2;

        cp_wait0();
        __syncthreads();

        if (t < 8) {
            const int nK = (t & 1) ? 1 : 3;
            const int nV = (t & 1) ? 2 : 0;
            const uint32_t* srcK = wK + (t + 1) * 2048;
            const uint32_t* srcV = wV + (t + 1) * 2048;
            #pragma unroll
            for (int i = 0; i < 2; i++) { int o = (tid + i * 256) * 4; cp16(Bf + nK * 2048 + o, srcK + o); }
            #pragma unroll
            for (int i = 0; i < 2; i++) { int o = (tid + i * 256) * 4; cp16(Bf + nV * 2048 + o, srcV + o); }
            cp_commit();
        } else {
            #pragma unroll
            for (int i = 0; i < 2; i++) { int o = (tid + i * 256) * 4; cp16(Bf + 3 * 2048 + o, wF1 + o); }
            cp_commit();
        }

        const int toff = ((t / 3) * HW2 + (t % 3)) * PSTH;
        const __half* A0 = haloH + off0 + toff;
        const __half* A8 = haloH + off8 + toff;

        // K_t GEMM -> scores
        float acc[8][4] = {};
        gemm64h(acc, Bf + sK * 2048 + lane * 2, A0, A8);

        float p[4] = {0.f, 0.f, 0.f, 0.f};
        #pragma unroll
        for (int nf = 0; nf < 8; nf++) {
            const int hd = nf >> 2;
            p[hd]     += acc[nf][0] * q[nf][0] + acc[nf][1] * q[nf][1];
            p[2 + hd] += acc[nf][2] * q[nf][2] + acc[nf][3] * q[nf][3];
        }
        float e[4], scale[4];
        #pragma unroll
        for (int v = 0; v < 4; v++) {
            p[v] += __shfl_xor_sync(0xffffffffu, p[v], 1);
            p[v] += __shfl_xor_sync(0xffffffffu, p[v], 2);
            float s = p[v] * (1.0f / 3.0f);
            float mn = fmaxf(mrun[v], s);
            scale[v] = __expf(mrun[v] - mn);
            e[v]     = __expf(s - mn);
            denom[v] = denom[v] * scale[v] + e[v];
            mrun[v]  = mn;
        }

        // V_t GEMM -> weighted accumulate with rescale
        #pragma unroll
        for (int nf = 0; nf < 8; nf++)
            #pragma unroll
            for (int j = 0; j < 4; j++) acc[nf][j] = 0.f;
        gemm64h(acc, Bf + sV * 2048 + lane * 2, A0, A8);

        #pragma unroll
        for (int nf = 0; nf < 8; nf++) {
            const int hd = nf >> 2;
            attn[nf][0] = attn[nf][0] * scale[hd]     + e[hd]     * acc[nf][0];
            attn[nf][1] = attn[nf][1] * scale[hd]     + e[hd]     * acc[nf][1];
            attn[nf][2] = attn[nf][2] * scale[2 + hd] + e[2 + hd] * acc[nf][2];
            attn[nf][3] = attn[nf][3] * scale[2 + hd] + e[2 + hd] * acc[nf][3];
        }
    }

    float inv[4];
    #pragma unroll
    for (int v = 0; v < 4; v++) inv[v] = 1.0f / denom[v];

    // ---- ff1 (slot3). attn -> fp16 smem tile -> GEMM -> t1 (fp16) ----
    cp_wait0();
    __syncthreads();

    __half* Ast = haloH;   // reuse
    #pragma unroll
    for (int nf = 0; nf < 8; nf++) {
        const int hd = nf >> 2;
        int col = nf * 8 + lc * 2;
        __half2 h0 = __floats2half2_rn(attn[nf][0] * inv[hd],     attn[nf][1] * inv[hd]);
        __half2 h1 = __floats2half2_rn(attn[nf][2] * inv[2 + hd], attn[nf][3] * inv[2 + hd]);
        *(uint32_t*)&Ast[(warp * 16 + lr) * PSTH + col]     = *(uint32_t*)&h0;
        *(uint32_t*)&Ast[(warp * 16 + lr + 8) * PSTH + col] = *(uint32_t*)&h1;
    }
    __syncthreads();

    float acc[8][4] = {};
    gemm64h(acc, Bf + 3 * 2048 + lane * 2,
            Ast + (warp * 16 + lr) * PSTH + 2 * lc,
            Ast + (warp * 16 + lr + 8) * PSTH + 2 * lc);

    const int ygl = y0 + warp;
    const size_t p0 = ((size_t)b * HH + ygl) * WW + x0 + lr;
    const size_t p1 = p0 + 8;
    #pragma unroll
    for (int nf = 0; nf < 8; nf++) {
        int col = nf * 8 + lc * 2;
        float b0 = bias1[col], b1 = bias1[col + 1];
        __half2 h0 = __floats2half2_rn(fmaxf(acc[nf][0] + b0, 0.f), fmaxf(acc[nf][1] + b1, 0.f));
        __half2 h1 = __floats2half2_rn(fmaxf(acc[nf][2] + b0, 0.f), fmaxf(acc[nf][3] + b1, 0.f));
        *(__half2*)(t1 + p0 * 64 + col) = h0;
        *(__half2*)(t1 + p1 * 64 + col) = h1;
    }
}

// ---------------------------------------------------------------------------
// fp16 3x3 conv (unchanged from R9; conv2 input now fp16).
// ---------------------------------------------------------------------------
template <bool IN_HALF, int CIN, int COUT_TOT, int SPLIT, bool OUT_HALF>
__global__ __launch_bounds__(128, 3) void conv_fp16(
    const void* __restrict__ in_, const uint32_t* __restrict__ wfrag,
    const float* __restrict__ bias, void* __restrict__ out_)
{
    constexpr int HW2 = 18, PSTH = 72;
    constexpr int HALO_H = 10 * HW2 * PSTH;
    constexpr int CHUNKS = CIN / 64;
    constexpr int WTAP = 2048;
    constexpr int CPT = WTAP / 4 / 128;
    constexpr int MFS = 2;

    extern __shared__ char smraw[];
    __half*   haloH = (__half*)smraw;
    uint32_t* Bf    = (uint32_t*)(smraw + HALO_H * 2);

    const int x0 = blockIdx.x * 16;
    const int y0 = blockIdx.y * 8;
    const int b  = blockIdx.z / SPLIT;
    const int cb = blockIdx.z % SPLIT;
    const int co0 = cb * 64;
    const int tid = threadIdx.x;
    const int warp = tid >> 5, lane = tid & 31;
    const int lr = lane >> 2, lc = lane & 3;

    float acc[MFS][8][4] = {};

    int pixoff[MFS][2];
    #pragma unroll
    for (int mf = 0; mf < MFS; mf++)
        #pragma unroll
        for (int r8 = 0; r8 < 2; r8++) {
            int m = warp * 32 + mf * 16 + r8 * 8 + lr;
            int py = m >> 4, px = m & 15;
            pixoff[mf][r8] = (py * HW2 + px) * PSTH;
        }

    for (int ch = 0; ch < CHUNKS; ch++) {
        const int cin0 = ch * 64;
        __syncthreads();

        {
            const uint32_t* src = wfrag + (size_t)(0 * CHUNKS * SPLIT + ch * SPLIT + cb) * WTAP;
            #pragma unroll
            for (int i = 0; i < CPT; i++) { int o = (tid + i * 128) * 4; cp16(Bf + o, src + o); }
            cp_commit();
        }

        if (IN_HALF) {
            const __half* in = (const __half*)in_;
            for (int idx = tid * 8; idx < 10 * HW2 * 64; idx += 128 * 8) {
                int c = idx & 63;
                int sp = idx >> 6;
                int hy = sp / HW2, hx = sp - hy * HW2;
                int gy = y0 + hy - 1, gx = x0 + hx - 1;
                uint4 v = make_uint4(0u, 0u, 0u, 0u);
                if ((unsigned)gy < HH && (unsigned)gx < WW)
                    v = *(const uint4*)(in + (((size_t)b * HH + gy) * WW + gx) * CIN + cin0 + c);
                *(uint4*)(haloH + sp * PSTH + c) = v;
            }
        } else {
            const float* in = (const float*)in_;
            for (int idx = tid * 4; idx < 10 * HW2 * 64; idx += 128 * 4) {
                int c = idx & 63;
                int sp = idx >> 6;
                int hy = sp / HW2, hx = sp - hy * HW2;
                int gy = y0 + hy - 1, gx = x0 + hx - 1;
                float4 v = make_float4(0.f, 0.f, 0.f, 0.f);
                if ((unsigned)gy < HH && (unsigned)gx < WW)
                    v = *(const float4*)(in + (((size_t)b * HH + gy) * WW + gx) * CIN + cin0 + c);
                __half2 h01 = __floats2half2_rn(v.x, v.y);
                __half2 h23 = __floats2half2_rn(v.z, v.w);
                *(uint2*)(haloH + sp * PSTH + c) =
                    make_uint2(*(uint32_t*)&h01, *(uint32_t*)&h23);
            }
        }
        cp_wait0();
        __syncthreads();

        for (int t = 0; t < 9; t++) {
            if (t < 8) {
                uint32_t* nb = Bf + ((t + 1) & 1) * WTAP;
                const uint32_t* src = wfrag + (size_t)((t + 1) * CHUNKS * SPLIT + ch * SPLIT + cb) * WTAP;
                #pragma unroll
                for (int i = 0; i < CPT; i++) { int o = (tid + i * 128) * 4; cp16(nb + o, src + o); }
                cp_commit();
            }

            const uint32_t* Bc = Bf + (t & 1) * WTAP;
            const int toff = ((t / 3) * HW2 + (t % 3)) * PSTH;

            #pragma unroll
            for (int ks16 = 0; ks16 < 4; ks16++) {
                uint32_t a[MFS][4];
                #pragma unroll
                for (int mf = 0; mf < MFS; mf++) {
                    const __half* b0 = haloH + pixoff[mf][0] + toff + ks16 * 16 + 2 * lc;
                    const __half* b1 = haloH + pixoff[mf][1] + toff + ks16 * 16 + 2 * lc;
                    a[mf][0] = *(const uint32_t*)b0;
                    a[mf][1] = *(const uint32_t*)b1;
                    a[mf][2] = *(const uint32_t*)(b0 + 8);
                    a[mf][3] = *(const uint32_t*)(b1 + 8);
                }
                #pragma unroll
                for (int nf = 0; nf < 8; nf++) {
                    uint2 bv = *(const uint2*)&Bc[(ks16 * 8 + nf) * 64 + lane * 2];
                    #pragma unroll
                    for (int mf = 0; mf < MFS; mf++)
                        mma16h(acc[mf][nf], a[mf], bv);
                }
            }

            if (t < 8) { cp_wait0(); __syncthreads(); }
        }
    }

    #pragma unroll
    for (int mf = 0; mf < MFS; mf++) {
        #pragma unroll
        for (int r8 = 0; r8 < 2; r8++) {
            int m = warp * 32 + mf * 16 + r8 * 8 + lr;
            int py = m >> 4, px = m & 15;
            int y = y0 + py, xx = x0 + px;
            size_t base = (((size_t)b * HH + y) * WW + xx) * COUT_TOT + co0;
            #pragma unroll
            for (int nf = 0; nf < 8; nf++) {
                int n = nf * 8 + lc * 2;
                float vx = fmaxf(acc[mf][nf][r8 * 2 + 0] + bias[co0 + n], 0.f);
                float vy = fmaxf(acc[mf][nf][r8 * 2 + 1] + bias[co0 + n + 1], 0.f);
                if (OUT_HALF) {
                    __half2 h = __floats2half2_rn(vx, vy);
                    *(__half2*)((__half*)out_ + base + n) = h;
                } else {
                    *(float2*)((float*)out_ + base + n) = make_float2(vx, vy);
                }
            }
        }
    }
}

// ---------------------------------------------------------------------------
// Launch
// ---------------------------------------------------------------------------
extern "C" void kernel_launch(void* const* d_in, const int* in_sizes, int n_in,
                              void* d_out, int out_size)
{
    const float* x      = (const float*)d_in[0];
    const float* K_P    = (const float*)d_in[1];
    const float* V_P    = (const float*)d_in[2];
    const float* Q_P    = (const float*)d_in[3];
    const float* ff1_k  = (const float*)d_in[4];
    const float* ff1_b  = (const float*)d_in[5];
    const float* ff2_k  = (const float*)d_in[6];
    const float* ff2_b  = (const float*)d_in[7];
    const float* ff3_k  = (const float*)d_in[8];
    const float* ff3_b  = (const float*)d_in[9];
    float* out = (float*)d_out;

    __half *t1, *t2, *wKh, *wVh, *wQh, *wF1h, *wc2h, *wc3h;
    cudaGetSymbolAddress((void**)&t1,   g_t1);
    cudaGetSymbolAddress((void**)&t2,   g_t2);
    cudaGetSymbolAddress((void**)&wKh,  g_wKh);
    cudaGetSymbolAddress((void**)&wVh,  g_wVh);
    cudaGetSymbolAddress((void**)&wQh,  g_wQh);
    cudaGetSymbolAddress((void**)&wF1h, g_wF1h);
    cudaGetSymbolAddress((void**)&wc2h, g_wc2h);
    cudaGetSymbolAddress((void**)&wc3h, g_wc3h);

    const int FUSED_SMEM = 180 * 72 * 2 + 4 * 2048 * 4;      // 58688
    const int CONV_SMEM  = 180 * 72 * 2 + 2 * 2048 * 4;      // 42304

    cudaFuncSetAttribute(attn_fused, cudaFuncAttributeMaxDynamicSharedMemorySize, FUSED_SMEM);
    cudaFuncSetAttribute((conv_fp16<true, 64, 128, 2, true>), cudaFuncAttributeMaxDynamicSharedMemorySize, CONV_SMEM);
    cudaFuncSetAttribute((conv_fp16<true, 128, 64, 1, false>), cudaFuncAttributeMaxDynamicSharedMemorySize, CONV_SMEM);

    prep_w<<<896, 256>>>(K_P, V_P, Q_P, ff1_k, ff2_k, ff3_k);

    // Fused fp16 projections + online-softmax attention + ff1
    attn_fused<<<dim3(WW / 16, HH / 8, BB), 256, FUSED_SMEM>>>(
        x, (const uint32_t*)wQh, (const uint32_t*)wKh, (const uint32_t*)wVh,
        (const uint32_t*)wF1h, ff1_b, t1);

    // fp16 convs
    conv_fp16<true, 64, 128, 2, true><<<dim3(WW / 16, HH / 8, BB * 2), 128, CONV_SMEM>>>(
        t1, (const uint32_t*)wc2h, ff2_b, t2);
    conv_fp16<true, 128, 64, 1, false><<<dim3(WW / 16, HH / 8, BB), 128, CONV_SMEM>>>(
        t2, (const uint32_t*)wc3h, ff3_b, out);
}